// round 1
// baseline (speedup 1.0000x reference)
#include <cuda_runtime.h>

// ---------------------------------------------------------------------------
// WaveletAttention: 3-level MODWT (db4, 8-tap circular dilated convs) -> MHA
// B=4, L=2048, D=512, H=8, dh=64
// ---------------------------------------------------------------------------

#define Bn  4
#define Ln  2048
#define Dn  512
#define Hn  8
#define DHn 64
#define NBD (Bn * Ln * Dn)   // 4,194,304

// Scratch (sanctioned __device__ globals; no allocations)
__device__ float g_v0[NBD];
__device__ float g_v1[NBD];
__device__ float g_v2[NBD];
__device__ float g_q [NBD];
__device__ float g_k [NBD];
__device__ float g_vv[NBD];

// ---------------------------------------------------------------------------
// 8-tap circular dilated convolution along L.
// out[b,t,d] = sum_k tap[k] * in[b, (t - dil*k) mod L, d]
// taps read from row 0 of the dense filter matrix: tap[k] = frow[(L - dil*k) mod L]
// ---------------------------------------------------------------------------
__global__ __launch_bounds__(256) void conv_kernel(
    const float* __restrict__ in, float* __restrict__ out,
    const float* __restrict__ frow, int dil)
{
    int idx = blockIdx.x * 256 + threadIdx.x;          // over B*L*D
    int d = idx & (Dn - 1);
    int t = (idx >> 9) & (Ln - 1);                     // Dn = 2^9
    int b = idx >> 20;                                 // Ln*Dn = 2^20
    const float* inb = in + ((long)b << 20);
    float acc = 0.f;
#pragma unroll
    for (int k = 0; k < 8; k++) {
        float tap = __ldg(&frow[(Ln - dil * k) & (Ln - 1)]);  // uniform, L1-hit
        int src = (t - dil * k) & (Ln - 1);
        acc += tap * inb[(src << 9) + d];
    }
    out[idx] = acc;
}

// ---------------------------------------------------------------------------
// fp32 flash attention. Grid: (L/BQ, B*H). 256 threads, 4x4 register tile.
// Thread (tx = tid&15, ty = tid>>4): q-rows ty*4..+3, key/dh cols tx+16j.
// smem: Qs[64][64], Ks[64][65], Vs[64][64], Ps[64][68]  (66,816 B dynamic)
// ---------------------------------------------------------------------------
#define BQ 64
#define BK 64
#define QS 64
#define KS 65
#define VS 64
#define PS 68
#define ATTN_SMEM ((64*QS + 64*KS + 64*VS + 64*PS) * 4)

__global__ __launch_bounds__(256) void attn_kernel(
    const float* __restrict__ Q, const float* __restrict__ K,
    const float* __restrict__ V, float* __restrict__ O)
{
    extern __shared__ float sm[];
    float* Qs = sm;
    float* Ks = Qs + 64 * QS;
    float* Vs = Ks + 64 * KS;
    float* Ps = Vs + 64 * VS;

    const int tid = threadIdx.x;
    const int tx = tid & 15;
    const int ty = tid >> 4;
    const int bh = blockIdx.y;
    const int b = bh >> 3, h = bh & 7;
    const int q0 = blockIdx.x * BQ;

    const float* Qg = Q + ((long)b * Ln + q0) * Dn + h * DHn;
    const float* Kg = K + (long)b * Ln * Dn + h * DHn;
    const float* Vg = V + (long)b * Ln * Dn + h * DHn;

    const float scale = 0.125f;  // 1/sqrt(64), folded into Q

    // Load Q tile (scaled), float4
#pragma unroll
    for (int i = 0; i < 4; i++) {
        int e4 = tid + i * 256;
        int r = e4 >> 4, c4 = e4 & 15;
        float4 v = *(const float4*)(Qg + (long)r * Dn + c4 * 4);
        v.x *= scale; v.y *= scale; v.z *= scale; v.w *= scale;
        *(float4*)(Qs + r * QS + c4 * 4) = v;
    }

    float m[4], l[4], acc[4][4];
#pragma unroll
    for (int i = 0; i < 4; i++) {
        m[i] = -1e30f; l[i] = 0.f;
#pragma unroll
        for (int j = 0; j < 4; j++) acc[i][j] = 0.f;
    }
    __syncthreads();

    for (int k0 = 0; k0 < Ln; k0 += BK) {
        // Load K (scalar stores, stride 65: conflict-free strided reads later)
        // and V (float4, natural layout)
#pragma unroll
        for (int i = 0; i < 4; i++) {
            int e4 = tid + i * 256;
            int r = e4 >> 4, c4 = e4 & 15;
            float4 kv = *(const float4*)(Kg + (long)(k0 + r) * Dn + c4 * 4);
            float* kd = Ks + r * KS + c4 * 4;
            kd[0] = kv.x; kd[1] = kv.y; kd[2] = kv.z; kd[3] = kv.w;
            float4 vv = *(const float4*)(Vg + (long)(k0 + r) * Dn + c4 * 4);
            *(float4*)(Vs + r * VS + c4 * 4) = vv;
        }
        __syncthreads();

        // S = Q @ K^T (outer-product over kk)
        float s[4][4];
#pragma unroll
        for (int i = 0; i < 4; i++)
#pragma unroll
            for (int j = 0; j < 4; j++) s[i][j] = 0.f;

#pragma unroll 16
        for (int kk = 0; kk < 64; kk++) {
            float qv[4], kv[4];
#pragma unroll
            for (int i = 0; i < 4; i++) qv[i] = Qs[(ty * 4 + i) * QS + kk];
#pragma unroll
            for (int j = 0; j < 4; j++) kv[j] = Ks[(tx + 16 * j) * KS + kk];
#pragma unroll
            for (int i = 0; i < 4; i++)
#pragma unroll
                for (int j = 0; j < 4; j++) s[i][j] += qv[i] * kv[j];
        }

        // Online softmax (row stats replicated across the 16 tx threads)
#pragma unroll
        for (int i = 0; i < 4; i++) {
            float mx = fmaxf(fmaxf(s[i][0], s[i][1]), fmaxf(s[i][2], s[i][3]));
#pragma unroll
            for (int o = 8; o; o >>= 1)
                mx = fmaxf(mx, __shfl_xor_sync(0xffffffffu, mx, o, 16));
            float mn = fmaxf(m[i], mx);
            float corr = __expf(m[i] - mn);
            m[i] = mn;
            float ls = 0.f;
#pragma unroll
            for (int j = 0; j < 4; j++) {
                float p = __expf(s[i][j] - mn);
                s[i][j] = p;
                ls += p;
            }
#pragma unroll
            for (int o = 8; o; o >>= 1)
                ls += __shfl_xor_sync(0xffffffffu, ls, o, 16);
            l[i] = l[i] * corr + ls;
#pragma unroll
            for (int j = 0; j < 4; j++) {
                acc[i][j] *= corr;
                Ps[(ty * 4 + i) * PS + tx + 16 * j] = s[i][j];
            }
        }
        __syncwarp();  // Ps rows are produced/consumed within one half-warp

        // O += P @ V
#pragma unroll 16
        for (int kk = 0; kk < 64; kk++) {
            float pv[4], vv[4];
#pragma unroll
            for (int i = 0; i < 4; i++) pv[i] = Ps[(ty * 4 + i) * PS + kk];
#pragma unroll
            for (int j = 0; j < 4; j++) vv[j] = Vs[kk * VS + tx + 16 * j];
#pragma unroll
            for (int i = 0; i < 4; i++)
#pragma unroll
                for (int j = 0; j < 4; j++) acc[i][j] += pv[i] * vv[j];
        }
        __syncthreads();  // protect Ks/Vs before next tile's load
    }

    // Epilogue
#pragma unroll
    for (int i = 0; i < 4; i++) {
        float inv = 1.f / l[i];
        long row = (long)b * Ln + q0 + ty * 4 + i;
#pragma unroll
        for (int j = 0; j < 4; j++)
            O[row * Dn + h * DHn + tx + 16 * j] = acc[i][j] * inv;
    }
}

// ---------------------------------------------------------------------------
extern "C" void kernel_launch(void* const* d_in, const int* in_sizes, int n_in,
                              void* d_out, int out_size)
{
    const float* x  = (const float*)d_in[0];
    const float* vf = (const float*)d_in[1];  // [3, L, L] lowpass cascade
    const float* wf = (const float*)d_in[2];  // [3, L, L] highpass
    float* out = (float*)d_out;

    float *v0, *v1, *v2, *q, *k, *v;
    cudaGetSymbolAddress((void**)&v0, g_v0);
    cudaGetSymbolAddress((void**)&v1, g_v1);
    cudaGetSymbolAddress((void**)&v2, g_v2);
    cudaGetSymbolAddress((void**)&q,  g_q);
    cudaGetSymbolAddress((void**)&k,  g_k);
    cudaGetSymbolAddress((void**)&v,  g_vv);

    const size_t LL = (size_t)Ln * Ln;
    const int cblocks = NBD / 256;

    // Lowpass cascade
    conv_kernel<<<cblocks, 256>>>(x,  v0, vf,          1);
    conv_kernel<<<cblocks, 256>>>(v0, v1, vf + LL,     2);
    conv_kernel<<<cblocks, 256>>>(v1, v2, vf + 2 * LL, 4);
    // Highpass per level -> Q, K, V
    conv_kernel<<<cblocks, 256>>>(v0, q,  wf,          1);
    conv_kernel<<<cblocks, 256>>>(v1, k,  wf + LL,     2);
    conv_kernel<<<cblocks, 256>>>(v2, v,  wf + 2 * LL, 4);

    cudaFuncSetAttribute(attn_kernel,
                         cudaFuncAttributeMaxDynamicSharedMemorySize, ATTN_SMEM);
    dim3 grid(Ln / BQ, Bn * Hn);  // (32, 32)
    attn_kernel<<<grid, 256, ATTN_SMEM>>>(q, k, v, out);
}

// round 3
// speedup vs baseline: 1.2897x; 1.2897x over previous
#include <cuda_runtime.h>

// ---------------------------------------------------------------------------
// WaveletAttention: 3-level MODWT (db4, 8-tap circular dilated convs) -> MHA
// B=4, L=2048, D=512, H=8, dh=64
// Round 3: 3xTF32 (hi/lo split) mma.sync flash attention  — fp32-accurate
// ---------------------------------------------------------------------------

#define Bn  4
#define Ln  2048
#define Dn  512
#define Hn  8
#define NBD (Bn * Ln * Dn)   // 4,194,304

__device__ float g_v0[NBD];
__device__ float g_v1[NBD];
__device__ float g_v2[NBD];
__device__ float g_q [NBD];
__device__ float g_k [NBD];
__device__ float g_vv[NBD];

// ---------------------------------------------------------------------------
__device__ __forceinline__ unsigned f2tf(float f) {
    unsigned u;
    asm("cvt.rna.tf32.f32 %0, %1;" : "=r"(u) : "f"(f));
    return u;
}
// hi/lo split: x ≈ hi + lo, both exactly representable in tf32
__device__ __forceinline__ void split_tf(float x, unsigned& hi, unsigned& lo) {
    hi = f2tf(x);
    lo = f2tf(x - __uint_as_float(hi));
}

__device__ __forceinline__ void mma_tf32(float* c, const unsigned* a,
                                         unsigned b0, unsigned b1) {
    asm("mma.sync.aligned.m16n8k8.row.col.f32.tf32.tf32.f32 "
        "{%0,%1,%2,%3}, {%4,%5,%6,%7}, {%8,%9}, {%0,%1,%2,%3};"
        : "+f"(c[0]), "+f"(c[1]), "+f"(c[2]), "+f"(c[3])
        : "r"(a[0]), "r"(a[1]), "r"(a[2]), "r"(a[3]), "r"(b0), "r"(b1));
}

// ---------------------------------------------------------------------------
// Vectorized 8-tap circular dilated conv
// ---------------------------------------------------------------------------
__global__ __launch_bounds__(256) void conv1_kernel(
    const float* __restrict__ in, float* __restrict__ out,
    const float* __restrict__ frow, int dil)
{
    int idx4 = blockIdx.x * 256 + threadIdx.x;     // over NBD/4
    int d4 = idx4 & 127;
    int t  = (idx4 >> 7) & (Ln - 1);
    int b  = idx4 >> 18;
    const float* inb = in + ((long)b << 20) + (d4 << 2);
    float4 acc = {0.f, 0.f, 0.f, 0.f};
#pragma unroll
    for (int k = 0; k < 8; k++) {
        float tap = __ldg(&frow[(Ln - dil * k) & (Ln - 1)]);
        int src = (t - dil * k) & (Ln - 1);
        float4 v = *(const float4*)(inb + (src << 9));
        acc.x += tap * v.x; acc.y += tap * v.y;
        acc.z += tap * v.z; acc.w += tap * v.w;
    }
    *(float4*)(out + ((long)idx4 << 2)) = acc;
}

__global__ __launch_bounds__(256) void conv2_kernel(
    const float* __restrict__ in,
    float* __restrict__ outA, const float* __restrict__ frowA, int dilA,
    float* __restrict__ outB, const float* __restrict__ frowB, int dilB)
{
    int idx4 = blockIdx.x * 256 + threadIdx.x;
    int d4 = idx4 & 127;
    int t  = (idx4 >> 7) & (Ln - 1);
    int b  = idx4 >> 18;
    const float* inb = in + ((long)b << 20) + (d4 << 2);
    float4 aA = {0.f, 0.f, 0.f, 0.f};
    float4 aB = {0.f, 0.f, 0.f, 0.f};
#pragma unroll
    for (int k = 0; k < 8; k++) {
        float tap = __ldg(&frowA[(Ln - dilA * k) & (Ln - 1)]);
        int src = (t - dilA * k) & (Ln - 1);
        float4 v = *(const float4*)(inb + (src << 9));
        aA.x += tap * v.x; aA.y += tap * v.y;
        aA.z += tap * v.z; aA.w += tap * v.w;
    }
#pragma unroll
    for (int k = 0; k < 8; k++) {
        float tap = __ldg(&frowB[(Ln - dilB * k) & (Ln - 1)]);
        int src = (t - dilB * k) & (Ln - 1);
        float4 v = *(const float4*)(inb + (src << 9));
        aB.x += tap * v.x; aB.y += tap * v.y;
        aB.z += tap * v.z; aB.w += tap * v.w;
    }
    *(float4*)(outA + ((long)idx4 << 2)) = aA;
    *(float4*)(outB + ((long)idx4 << 2)) = aB;
}

// ---------------------------------------------------------------------------
// 3xTF32 flash attention. Grid (L/64, B*H). 128 threads = 4 warps.
// Each operand split hi/lo; each MMA triple: hi*hi + hi*lo + lo*hi.
// smem: Kh/Kl[64][68], Vh/Vl[64][72], Ph/Pl[64][68]  = 106,496 B
// ---------------------------------------------------------------------------
#define STRK 68
#define STRV 72
#define STRP 68
#define ASMEM ((64 * (2*STRK + 2*STRV + 2*STRP)) * 4)

__global__ __launch_bounds__(128) void attn_kernel(
    const float* __restrict__ Qg, const float* __restrict__ Kgl,
    const float* __restrict__ Vgl, float* __restrict__ O)
{
    extern __shared__ unsigned sm_u[];
    unsigned* Kh = sm_u;
    unsigned* Kl = Kh + 64 * STRK;
    unsigned* Vh = Kl + 64 * STRK;
    unsigned* Vl = Vh + 64 * STRV;
    unsigned* Ph = Vl + 64 * STRV;
    unsigned* Pl = Ph + 64 * STRP;

    const int tid = threadIdx.x;
    const int lane = tid & 31, warp = tid >> 5;
    const int g = lane >> 2, tg = lane & 3;
    const int bh = blockIdx.y;
    const int b = bh >> 3, h = bh & 7;
    const int q0 = blockIdx.x * 64;

    const float* Qp = Qg + ((long)b * Ln + q0) * Dn + h * 64;
    const float* Kp = Kgl + (long)b * Ln * Dn + h * 64;
    const float* Vp = Vgl + (long)b * Ln * Dn + h * 64;

    // ---- stage scaled Q into Ph (raw f32 bits), then build hi/lo frags
#pragma unroll
    for (int i = 0; i < 8; i++) {
        int e4 = tid + i * 128;
        int r = e4 >> 4, c4 = e4 & 15;
        float4 v = *(const float4*)(Qp + (long)r * Dn + c4 * 4);
        unsigned* d = Ph + r * STRP + c4 * 4;
        d[0] = __float_as_uint(v.x * 0.125f);
        d[1] = __float_as_uint(v.y * 0.125f);
        d[2] = __float_as_uint(v.z * 0.125f);
        d[3] = __float_as_uint(v.w * 0.125f);
    }
    __syncthreads();

    unsigned qh[8][4], ql[8][4];
    {
        const unsigned* q0p = Ph + (warp * 16 + g) * STRP;
        const unsigned* q1p = q0p + 8 * STRP;
#pragma unroll
        for (int kt = 0; kt < 8; kt++) {
            split_tf(__uint_as_float(q0p[kt * 8 + tg]),     qh[kt][0], ql[kt][0]);
            split_tf(__uint_as_float(q1p[kt * 8 + tg]),     qh[kt][1], ql[kt][1]);
            split_tf(__uint_as_float(q0p[kt * 8 + tg + 4]), qh[kt][2], ql[kt][2]);
            split_tf(__uint_as_float(q1p[kt * 8 + tg + 4]), qh[kt][3], ql[kt][3]);
        }
    }
    __syncthreads();   // Ph reused as P buffer below

    float m_[2] = {-1e30f, -1e30f}, l_[2] = {0.f, 0.f};
    float oacc[8][4];
#pragma unroll
    for (int nt = 0; nt < 8; nt++)
#pragma unroll
        for (int j = 0; j < 4; j++) oacc[nt][j] = 0.f;

    for (int k0 = 0; k0 < Ln; k0 += 64) {
        __syncthreads();
        // ---- load K,V tile, split hi/lo at load
#pragma unroll
        for (int i = 0; i < 8; i++) {
            int e4 = tid + i * 128;
            int r = e4 >> 4, c4 = e4 & 15;
            float4 kv = *(const float4*)(Kp + (long)(k0 + r) * Dn + c4 * 4);
            unsigned* kdh = Kh + r * STRK + c4 * 4;
            unsigned* kdl = Kl + r * STRK + c4 * 4;
            split_tf(kv.x, kdh[0], kdl[0]); split_tf(kv.y, kdh[1], kdl[1]);
            split_tf(kv.z, kdh[2], kdl[2]); split_tf(kv.w, kdh[3], kdl[3]);
            float4 vv = *(const float4*)(Vp + (long)(k0 + r) * Dn + c4 * 4);
            unsigned* vdh = Vh + r * STRV + c4 * 4;
            unsigned* vdl = Vl + r * STRV + c4 * 4;
            split_tf(vv.x, vdh[0], vdl[0]); split_tf(vv.y, vdh[1], vdl[1]);
            split_tf(vv.z, vdh[2], vdl[2]); split_tf(vv.w, vdh[3], vdl[3]);
        }
        __syncthreads();

        // ---- S = Q @ K^T  (3xTF32)
        float sc[8][4];
#pragma unroll
        for (int nt = 0; nt < 8; nt++) {
            sc[nt][0] = sc[nt][1] = sc[nt][2] = sc[nt][3] = 0.f;
            const unsigned* krh = Kh + (nt * 8 + g) * STRK;
            const unsigned* krl = Kl + (nt * 8 + g) * STRK;
#pragma unroll
            for (int kt = 0; kt < 8; kt++) {
                unsigned bh0 = krh[kt * 8 + tg], bh1 = krh[kt * 8 + tg + 4];
                unsigned bl0 = krl[kt * 8 + tg], bl1 = krl[kt * 8 + tg + 4];
                mma_tf32(sc[nt], ql[kt], bh0, bh1);   // lo*hi
                mma_tf32(sc[nt], qh[kt], bl0, bl1);   // hi*lo
                mma_tf32(sc[nt], qh[kt], bh0, bh1);   // hi*hi
            }
        }

        // ---- online softmax
        float rmax[2] = {-1e30f, -1e30f};
#pragma unroll
        for (int nt = 0; nt < 8; nt++) {
            rmax[0] = fmaxf(rmax[0], fmaxf(sc[nt][0], sc[nt][1]));
            rmax[1] = fmaxf(rmax[1], fmaxf(sc[nt][2], sc[nt][3]));
        }
#pragma unroll
        for (int o = 1; o <= 2; o <<= 1) {
            rmax[0] = fmaxf(rmax[0], __shfl_xor_sync(0xffffffffu, rmax[0], o));
            rmax[1] = fmaxf(rmax[1], __shfl_xor_sync(0xffffffffu, rmax[1], o));
        }
        float corr[2];
#pragma unroll
        for (int r = 0; r < 2; r++) {
            float mn = fmaxf(m_[r], rmax[r]);
            corr[r] = __expf(m_[r] - mn);
            m_[r] = mn;
        }
        float rsum[2] = {0.f, 0.f};
        unsigned* p0h = Ph + (warp * 16 + g) * STRP;
        unsigned* p1h = p0h + 8 * STRP;
        unsigned* p0l = Pl + (warp * 16 + g) * STRP;
        unsigned* p1l = p0l + 8 * STRP;
#pragma unroll
        for (int nt = 0; nt < 8; nt++) {
            float p0 = __expf(sc[nt][0] - m_[0]);
            float p1 = __expf(sc[nt][1] - m_[0]);
            float p2 = __expf(sc[nt][2] - m_[1]);
            float p3 = __expf(sc[nt][3] - m_[1]);
            rsum[0] += p0 + p1; rsum[1] += p2 + p3;
            split_tf(p0, p0h[nt * 8 + 2 * tg],     p0l[nt * 8 + 2 * tg]);
            split_tf(p1, p0h[nt * 8 + 2 * tg + 1], p0l[nt * 8 + 2 * tg + 1]);
            split_tf(p2, p1h[nt * 8 + 2 * tg],     p1l[nt * 8 + 2 * tg]);
            split_tf(p3, p1h[nt * 8 + 2 * tg + 1], p1l[nt * 8 + 2 * tg + 1]);
        }
#pragma unroll
        for (int o = 1; o <= 2; o <<= 1) {
            rsum[0] += __shfl_xor_sync(0xffffffffu, rsum[0], o);
            rsum[1] += __shfl_xor_sync(0xffffffffu, rsum[1], o);
        }
        l_[0] = l_[0] * corr[0] + rsum[0];
        l_[1] = l_[1] * corr[1] + rsum[1];
#pragma unroll
        for (int nt = 0; nt < 8; nt++) {
            oacc[nt][0] *= corr[0]; oacc[nt][1] *= corr[0];
            oacc[nt][2] *= corr[1]; oacc[nt][3] *= corr[1];
        }
        __syncwarp();   // P stores visible within warp

        // ---- O += P @ V  (3xTF32)
#pragma unroll
        for (int kt = 0; kt < 8; kt++) {
            unsigned pah[4], pal[4];
            pah[0] = p0h[kt * 8 + tg];     pal[0] = p0l[kt * 8 + tg];
            pah[1] = p1h[kt * 8 + tg];     pal[1] = p1l[kt * 8 + tg];
            pah[2] = p0h[kt * 8 + tg + 4]; pal[2] = p0l[kt * 8 + tg + 4];
            pah[3] = p1h[kt * 8 + tg + 4]; pal[3] = p1l[kt * 8 + tg + 4];
            const unsigned* v0h = Vh + (kt * 8 + tg) * STRV;
            const unsigned* v1h = Vh + (kt * 8 + tg + 4) * STRV;
            const unsigned* v0l = Vl + (kt * 8 + tg) * STRV;
            const unsigned* v1l = Vl + (kt * 8 + tg + 4) * STRV;
#pragma unroll
            for (int nt = 0; nt < 8; nt++) {
                unsigned bh0 = v0h[nt * 8 + g], bh1 = v1h[nt * 8 + g];
                unsigned bl0 = v0l[nt * 8 + g], bl1 = v1l[nt * 8 + g];
                mma_tf32(oacc[nt], pal, bh0, bh1);   // lo*hi
                mma_tf32(oacc[nt], pah, bl0, bl1);   // hi*lo
                mma_tf32(oacc[nt], pah, bh0, bh1);   // hi*hi
            }
        }
    }

    // ---- epilogue
    float inv0 = 1.f / l_[0], inv1 = 1.f / l_[1];
    long row0 = (long)b * Ln + q0 + warp * 16 + g;
    long row1 = row0 + 8;
#pragma unroll
    for (int nt = 0; nt < 8; nt++) {
        int col = h * 64 + nt * 8 + 2 * tg;
        float2 v0 = {oacc[nt][0] * inv0, oacc[nt][1] * inv0};
        float2 v1 = {oacc[nt][2] * inv1, oacc[nt][3] * inv1};
        *(float2*)(O + row0 * Dn + col) = v0;
        *(float2*)(O + row1 * Dn + col) = v1;
    }
}

// ---------------------------------------------------------------------------
extern "C" void kernel_launch(void* const* d_in, const int* in_sizes, int n_in,
                              void* d_out, int out_size)
{
    const float* x  = (const float*)d_in[0];
    const float* vf = (const float*)d_in[1];
    const float* wf = (const float*)d_in[2];
    float* out = (float*)d_out;

    float *v0, *v1, *v2, *q, *k, *v;
    cudaGetSymbolAddress((void**)&v0, g_v0);
    cudaGetSymbolAddress((void**)&v1, g_v1);
    cudaGetSymbolAddress((void**)&v2, g_v2);
    cudaGetSymbolAddress((void**)&q,  g_q);
    cudaGetSymbolAddress((void**)&k,  g_k);
    cudaGetSymbolAddress((void**)&v,  g_vv);

    const size_t LL = (size_t)Ln * Ln;
    const int cblocks = (NBD / 4) / 256;

    conv1_kernel<<<cblocks, 256>>>(x, v0, vf, 1);
    conv2_kernel<<<cblocks, 256>>>(v0, q, wf, 1, v1, vf + LL, 2);
    conv2_kernel<<<cblocks, 256>>>(v1, k, wf + LL, 2, v2, vf + 2 * LL, 4);
    conv1_kernel<<<cblocks, 256>>>(v2, v, wf + 2 * LL, 4);

    cudaFuncSetAttribute(attn_kernel,
                         cudaFuncAttributeMaxDynamicSharedMemorySize, ASMEM);
    dim3 grid(Ln / 64, Bn * Hn);
    attn_kernel<<<grid, 128, ASMEM>>>(q, k, v, out);
}

// round 4
// speedup vs baseline: 2.5612x; 1.9858x over previous
#include <cuda_runtime.h>
#include <cuda_fp16.h>

// ---------------------------------------------------------------------------
// WaveletAttention: 3-level MODWT (db4 dilated circular convs) -> MHA
// B=4, L=2048, D=512, H=8, dh=64
// Round 4: fp16 3x-split (hi/lo) m16n8k16 flash attention, precomputed splits
// ---------------------------------------------------------------------------

#define Bn  4
#define Ln  2048
#define Dn  512
#define Hn  8
#define NBD (Bn * Ln * Dn)   // 4,194,304

__device__ float  g_v0[NBD];
__device__ float  g_v1[NBD];
__device__ float  g_v2[NBD];
__device__ float  g_q [NBD];
__device__ float  g_vv[NBD];
__device__ __half g_kh [NBD];   // K hi, [B][L][D]
__device__ __half g_kl [NBD];   // K lo
__device__ __half g_vth[NBD];   // V^T hi, [B*H][64][L]
__device__ __half g_vtl[NBD];   // V^T lo

// ---------------------------------------------------------------------------
__device__ __forceinline__ void split_h2(float x, float y,
                                         unsigned& hi, unsigned& lo) {
    __half hx = __float2half_rn(x);
    __half hy = __float2half_rn(y);
    __half lx = __float2half_rn(x - __half2float(hx));
    __half ly = __float2half_rn(y - __half2float(hy));
    hi = ((unsigned)__half_as_ushort(hy) << 16) | __half_as_ushort(hx);
    lo = ((unsigned)__half_as_ushort(ly) << 16) | __half_as_ushort(lx);
}

__device__ __forceinline__ void mma_f16(float* c, const unsigned* a,
                                        unsigned b0, unsigned b1) {
    asm("mma.sync.aligned.m16n8k16.row.col.f32.f16.f16.f32 "
        "{%0,%1,%2,%3}, {%4,%5,%6,%7}, {%8,%9}, {%0,%1,%2,%3};"
        : "+f"(c[0]), "+f"(c[1]), "+f"(c[2]), "+f"(c[3])
        : "r"(a[0]), "r"(a[1]), "r"(a[2]), "r"(a[3]), "r"(b0), "r"(b1));
}

// ---------------------------------------------------------------------------
// 8-tap circular dilated convs (f32 outputs)
// ---------------------------------------------------------------------------
__global__ __launch_bounds__(256) void conv1_kernel(
    const float* __restrict__ in, float* __restrict__ out,
    const float* __restrict__ frow, int dil)
{
    int idx4 = blockIdx.x * 256 + threadIdx.x;
    int d4 = idx4 & 127;
    int t  = (idx4 >> 7) & (Ln - 1);
    int b  = idx4 >> 18;
    const float* inb = in + ((long)b << 20) + (d4 << 2);
    float4 acc = {0.f, 0.f, 0.f, 0.f};
#pragma unroll
    for (int k = 0; k < 8; k++) {
        float tap = __ldg(&frow[(Ln - dil * k) & (Ln - 1)]);
        int src = (t - dil * k) & (Ln - 1);
        float4 v = *(const float4*)(inb + (src << 9));
        acc.x += tap * v.x; acc.y += tap * v.y;
        acc.z += tap * v.z; acc.w += tap * v.w;
    }
    *(float4*)(out + ((long)idx4 << 2)) = acc;
}

// fused: A-output (f32) + B-output (f32), same input
__global__ __launch_bounds__(256) void conv2_kernel(
    const float* __restrict__ in,
    float* __restrict__ outA, const float* __restrict__ frowA, int dilA,
    float* __restrict__ outB, const float* __restrict__ frowB, int dilB)
{
    int idx4 = blockIdx.x * 256 + threadIdx.x;
    int d4 = idx4 & 127;
    int t  = (idx4 >> 7) & (Ln - 1);
    int b  = idx4 >> 18;
    const float* inb = in + ((long)b << 20) + (d4 << 2);
    float4 aA = {0.f, 0.f, 0.f, 0.f};
    float4 aB = {0.f, 0.f, 0.f, 0.f};
#pragma unroll
    for (int k = 0; k < 8; k++) {
        float tap = __ldg(&frowA[(Ln - dilA * k) & (Ln - 1)]);
        int src = (t - dilA * k) & (Ln - 1);
        float4 v = *(const float4*)(inb + (src << 9));
        aA.x += tap * v.x; aA.y += tap * v.y;
        aA.z += tap * v.z; aA.w += tap * v.w;
    }
#pragma unroll
    for (int k = 0; k < 8; k++) {
        float tap = __ldg(&frowB[(Ln - dilB * k) & (Ln - 1)]);
        int src = (t - dilB * k) & (Ln - 1);
        float4 v = *(const float4*)(inb + (src << 9));
        aB.x += tap * v.x; aB.y += tap * v.y;
        aB.z += tap * v.z; aB.w += tap * v.w;
    }
    *(float4*)(outA + ((long)idx4 << 2)) = aA;
    *(float4*)(outB + ((long)idx4 << 2)) = aB;
}

// fused: A-output as fp16 hi/lo split + B-output f32 (used for K)
__global__ __launch_bounds__(256) void conv2s_kernel(
    const float* __restrict__ in,
    __half* __restrict__ outAh, __half* __restrict__ outAl,
    const float* __restrict__ frowA, int dilA,
    float* __restrict__ outB, const float* __restrict__ frowB, int dilB)
{
    int idx4 = blockIdx.x * 256 + threadIdx.x;
    int d4 = idx4 & 127;
    int t  = (idx4 >> 7) & (Ln - 1);
    int b  = idx4 >> 18;
    const float* inb = in + ((long)b << 20) + (d4 << 2);
    float4 aA = {0.f, 0.f, 0.f, 0.f};
    float4 aB = {0.f, 0.f, 0.f, 0.f};
#pragma unroll
    for (int k = 0; k < 8; k++) {
        float tap = __ldg(&frowA[(Ln - dilA * k) & (Ln - 1)]);
        int src = (t - dilA * k) & (Ln - 1);
        float4 v = *(const float4*)(inb + (src << 9));
        aA.x += tap * v.x; aA.y += tap * v.y;
        aA.z += tap * v.z; aA.w += tap * v.w;
    }
#pragma unroll
    for (int k = 0; k < 8; k++) {
        float tap = __ldg(&frowB[(Ln - dilB * k) & (Ln - 1)]);
        int src = (t - dilB * k) & (Ln - 1);
        float4 v = *(const float4*)(inb + (src << 9));
        aB.x += tap * v.x; aB.y += tap * v.y;
        aB.z += tap * v.z; aB.w += tap * v.w;
    }
    unsigned h01, l01, h23, l23;
    split_h2(aA.x, aA.y, h01, l01);
    split_h2(aA.z, aA.w, h23, l23);
    *(uint2*)(outAh + ((long)idx4 << 2)) = make_uint2(h01, h23);
    *(uint2*)(outAl + ((long)idx4 << 2)) = make_uint2(l01, l23);
    *(float4*)(outB + ((long)idx4 << 2)) = aB;
}

// ---------------------------------------------------------------------------
// Transpose + split: v[b][t][h*64+dh] -> vth/vtl[bh][dh][t]  (fp16 hi/lo)
// grid (L/64, B*H), 256 threads
// ---------------------------------------------------------------------------
__global__ __launch_bounds__(256) void vtrans_kernel(
    const float* __restrict__ v,
    __half* __restrict__ vth, __half* __restrict__ vtl)
{
    __shared__ float tile[64][65];
    int t0 = blockIdx.x * 64;
    int bh = blockIdx.y;
    int b = bh >> 3, h = bh & 7;
    const float* src = v + ((long)b * Ln + t0) * Dn + h * 64;
#pragma unroll
    for (int it = 0; it < 16; it++) {
        int o = it * 256 + threadIdx.x;
        int r = o >> 6, c = o & 63;
        tile[r][c] = src[(long)r * Dn + c];
    }
    __syncthreads();
    __half* dh_ = vth + (long)bh * 64 * Ln + t0;
    __half* dl_ = vtl + (long)bh * 64 * Ln + t0;
#pragma unroll
    for (int it = 0; it < 16; it++) {
        int o = it * 256 + threadIdx.x;
        int key = o & 63, dh = o >> 6;
        float x = tile[key][dh];
        __half hi = __float2half_rn(x);
        __half lo = __float2half_rn(x - __half2float(hi));
        dh_[(long)dh * Ln + key] = hi;
        dl_[(long)dh * Ln + key] = lo;
    }
}

// ---------------------------------------------------------------------------
// fp16 3x-split flash attention. Grid (L/128, B*H), 256 threads = 8 warps.
// Warp owns 16 q-rows. smem rows stride 72 halfs (36 words) — conflict-free.
// smem: sKh/sKl[64][72], sVh/sVl[64][72] (V transposed: [dh][key]),
//       sPh/sPl[128][72]   -> 73,728 B
// ---------------------------------------------------------------------------
#define STRW 36   // words per smem row (72 halfs)
#define ASMEM ((4 * 64 * STRW + 2 * 128 * STRW) * 4)

__global__ __launch_bounds__(256, 2) void attn_kernel(
    const float* __restrict__ Qg,
    const __half* __restrict__ Khg, const __half* __restrict__ Klg,
    const __half* __restrict__ Vhg, const __half* __restrict__ Vlg,
    float* __restrict__ O)
{
    extern __shared__ unsigned sm_u[];
    unsigned* sKh = sm_u;
    unsigned* sKl = sKh + 64 * STRW;
    unsigned* sVh = sKl + 64 * STRW;
    unsigned* sVl = sVh + 64 * STRW;
    unsigned* sPh = sVl + 64 * STRW;
    unsigned* sPl = sPh + 128 * STRW;

    const int tid = threadIdx.x;
    const int lane = tid & 31, warp = tid >> 5;
    const int g = lane >> 2, tg = lane & 3;
    const int bh = blockIdx.y;
    const int b = bh >> 3, h = bh & 7;
    const int q0 = blockIdx.x * 128;

    // ---- Q fragments straight from global (scaled, split hi/lo)
    unsigned qah[4][4], qal[4][4];
    {
        const float* Qp = Qg + ((long)b * Ln + q0 + warp * 16) * Dn + h * 64;
#pragma unroll
        for (int kt = 0; kt < 4; kt++)
#pragma unroll
            for (int part = 0; part < 4; part++) {
                int row = g + (part & 1) * 8;
                int col = kt * 16 + ((part >> 1) << 3) + 2 * tg;
                float2 x = *(const float2*)(Qp + row * Dn + col);
                split_h2(x.x * 0.125f, x.y * 0.125f, qah[kt][part], qal[kt][part]);
            }
    }

    const __half* Kb  = Khg + (long)b * Ln * Dn + h * 64;
    const __half* Klb = Klg + (long)b * Ln * Dn + h * 64;
    const __half* Vb  = Vhg + (long)bh * 64 * Ln;
    const __half* Vlb = Vlg + (long)bh * 64 * Ln;

    float m_[2] = {-1e30f, -1e30f}, l_[2] = {0.f, 0.f};
    float oacc[8][4];
#pragma unroll
    for (int nt = 0; nt < 8; nt++)
#pragma unroll
        for (int j = 0; j < 4; j++) oacc[nt][j] = 0.f;

    unsigned* p0h = sPh + (warp * 16 + g) * STRW;
    unsigned* p1h = p0h + 8 * STRW;
    unsigned* p0l = sPl + (warp * 16 + g) * STRW;
    unsigned* p1l = p0l + 8 * STRW;

    for (int k0 = 0; k0 < Ln; k0 += 64) {
        __syncthreads();
        // ---- copy K hi/lo [64][64] and V^T hi/lo [64][64] tiles (pure uint4)
#pragma unroll
        for (int j = 0; j < 8; j++) {
            int flat = j * 256 + tid;
            int arr = flat >> 9, rem = flat & 511;
            int row = rem >> 3, c = rem & 7;
            const __half* src;
            unsigned* dst;
            if (arr == 0)      { src = Kb  + (long)(k0 + row) * Dn; dst = sKh; }
            else if (arr == 1) { src = Klb + (long)(k0 + row) * Dn; dst = sKl; }
            else if (arr == 2) { src = Vb  + (long)row * Ln + k0;   dst = sVh; }
            else               { src = Vlb + (long)row * Ln + k0;   dst = sVl; }
            uint4 val = *(const uint4*)(src + c * 8);
            *(uint4*)(dst + row * STRW + c * 4) = val;
        }
        __syncthreads();

        // ---- S = Q K^T  (fp16 3x: lo*hi + hi*lo + hi*hi)
        float sc[8][4];
#pragma unroll
        for (int nt = 0; nt < 8; nt++)
            sc[nt][0] = sc[nt][1] = sc[nt][2] = sc[nt][3] = 0.f;
#pragma unroll
        for (int kt = 0; kt < 4; kt++)
#pragma unroll
            for (int nt = 0; nt < 8; nt++) {
                const unsigned* krh = sKh + (nt * 8 + g) * STRW + kt * 8;
                const unsigned* krl = sKl + (nt * 8 + g) * STRW + kt * 8;
                unsigned b0h = krh[tg], b1h = krh[tg + 4];
                unsigned b0l = krl[tg], b1l = krl[tg + 4];
                mma_f16(sc[nt], qal[kt], b0h, b1h);
                mma_f16(sc[nt], qah[kt], b0l, b1l);
                mma_f16(sc[nt], qah[kt], b0h, b1h);
            }

        // ---- online softmax (rows g, g+8; cols 2tg,2tg+1 per nt)
        float rmax[2] = {-1e30f, -1e30f};
#pragma unroll
        for (int nt = 0; nt < 8; nt++) {
            rmax[0] = fmaxf(rmax[0], fmaxf(sc[nt][0], sc[nt][1]));
            rmax[1] = fmaxf(rmax[1], fmaxf(sc[nt][2], sc[nt][3]));
        }
#pragma unroll
        for (int o = 1; o <= 2; o <<= 1) {
            rmax[0] = fmaxf(rmax[0], __shfl_xor_sync(0xffffffffu, rmax[0], o));
            rmax[1] = fmaxf(rmax[1], __shfl_xor_sync(0xffffffffu, rmax[1], o));
        }
        float corr[2];
#pragma unroll
        for (int r = 0; r < 2; r++) {
            float mn = fmaxf(m_[r], rmax[r]);
            corr[r] = __expf(m_[r] - mn);
            m_[r] = mn;
        }
        float rsum[2] = {0.f, 0.f};
#pragma unroll
        for (int nt = 0; nt < 8; nt++) {
            float p0 = __expf(sc[nt][0] - m_[0]);
            float p1 = __expf(sc[nt][1] - m_[0]);
            float p2 = __expf(sc[nt][2] - m_[1]);
            float p3 = __expf(sc[nt][3] - m_[1]);
            rsum[0] += p0 + p1; rsum[1] += p2 + p3;
            unsigned h01, l01, h23, l23;
            split_h2(p0, p1, h01, l01);
            split_h2(p2, p3, h23, l23);
            p0h[nt * 4 + tg] = h01; p0l[nt * 4 + tg] = l01;
            p1h[nt * 4 + tg] = h23; p1l[nt * 4 + tg] = l23;
        }
#pragma unroll
        for (int o = 1; o <= 2; o <<= 1) {
            rsum[0] += __shfl_xor_sync(0xffffffffu, rsum[0], o);
            rsum[1] += __shfl_xor_sync(0xffffffffu, rsum[1], o);
        }
        l_[0] = l_[0] * corr[0] + rsum[0];
        l_[1] = l_[1] * corr[1] + rsum[1];
#pragma unroll
        for (int nt = 0; nt < 8; nt++) {
            oacc[nt][0] *= corr[0]; oacc[nt][1] *= corr[0];
            oacc[nt][2] *= corr[1]; oacc[nt][3] *= corr[1];
        }
        __syncwarp();   // P rows are per-warp

        // ---- O += P V  (fp16 3x; V^T gives contiguous key-pairs)
#pragma unroll
        for (int kt = 0; kt < 4; kt++) {
            unsigned pah[4], pal[4];
            pah[0] = p0h[kt * 8 + tg];     pal[0] = p0l[kt * 8 + tg];
            pah[1] = p1h[kt * 8 + tg];     pal[1] = p1l[kt * 8 + tg];
            pah[2] = p0h[kt * 8 + tg + 4]; pal[2] = p0l[kt * 8 + tg + 4];
            pah[3] = p1h[kt * 8 + tg + 4]; pal[3] = p1l[kt * 8 + tg + 4];
#pragma unroll
            for (int nt = 0; nt < 8; nt++) {
                const unsigned* vrh = sVh + (nt * 8 + g) * STRW + kt * 8;
                const unsigned* vrl = sVl + (nt * 8 + g) * STRW + kt * 8;
                unsigned b0h = vrh[tg], b1h = vrh[tg + 4];
                unsigned b0l = vrl[tg], b1l = vrl[tg + 4];
                mma_f16(oacc[nt], pal, b0h, b1h);
                mma_f16(oacc[nt], pah, b0l, b1l);
                mma_f16(oacc[nt], pah, b0h, b1h);
            }
        }
    }

    // ---- epilogue
    float inv0 = 1.f / l_[0], inv1 = 1.f / l_[1];
    long row0 = (long)b * Ln + q0 + warp * 16 + g;
    long row1 = row0 + 8;
#pragma unroll
    for (int nt = 0; nt < 8; nt++) {
        int col = h * 64 + nt * 8 + 2 * tg;
        float2 v0 = {oacc[nt][0] * inv0, oacc[nt][1] * inv0};
        float2 v1 = {oacc[nt][2] * inv1, oacc[nt][3] * inv1};
        *(float2*)(O + row0 * Dn + col) = v0;
        *(float2*)(O + row1 * Dn + col) = v1;
    }
}

// ---------------------------------------------------------------------------
extern "C" void kernel_launch(void* const* d_in, const int* in_sizes, int n_in,
                              void* d_out, int out_size)
{
    const float* x  = (const float*)d_in[0];
    const float* vf = (const float*)d_in[1];
    const float* wf = (const float*)d_in[2];
    float* out = (float*)d_out;

    float *v0, *v1, *v2, *q, *vv;
    __half *kh, *kl, *vth, *vtl;
    cudaGetSymbolAddress((void**)&v0,  g_v0);
    cudaGetSymbolAddress((void**)&v1,  g_v1);
    cudaGetSymbolAddress((void**)&v2,  g_v2);
    cudaGetSymbolAddress((void**)&q,   g_q);
    cudaGetSymbolAddress((void**)&vv,  g_vv);
    cudaGetSymbolAddress((void**)&kh,  g_kh);
    cudaGetSymbolAddress((void**)&kl,  g_kl);
    cudaGetSymbolAddress((void**)&vth, g_vth);
    cudaGetSymbolAddress((void**)&vtl, g_vtl);

    const size_t LL = (size_t)Ln * Ln;
    const int cblocks = (NBD / 4) / 256;

    // v0 = L0(x); {q = H0(v0), v1 = L1(v0)}; {khl = H1(v1), v2 = L2(v1)}; vv = H2(v2)
    conv1_kernel<<<cblocks, 256>>>(x, v0, vf, 1);
    conv2_kernel<<<cblocks, 256>>>(v0, q, wf, 1, v1, vf + LL, 2);
    conv2s_kernel<<<cblocks, 256>>>(v1, kh, kl, wf + LL, 2, v2, vf + 2 * LL, 4);
    conv1_kernel<<<cblocks, 256>>>(v2, vv, wf + 2 * LL, 4);
    vtrans_kernel<<<dim3(Ln / 64, Bn * Hn), 256>>>(vv, vth, vtl);

    cudaFuncSetAttribute(attn_kernel,
                         cudaFuncAttributeMaxDynamicSharedMemorySize, ASMEM);
    dim3 grid(Ln / 128, Bn * Hn);   // (16, 32)
    attn_kernel<<<grid, 256, ASMEM>>>(q, kh, kl, vth, vtl, out);
}

// round 8
// speedup vs baseline: 2.5856x; 1.0095x over previous
#include <cuda_runtime.h>
#include <cuda_fp16.h>
#include <cstdint>

// ---------------------------------------------------------------------------
// WaveletAttention: 3-level MODWT (db4 dilated circular convs) -> MHA
// B=4, L=2048, D=512, H=8, dh=64
// Round 8: fp16 3x-split (both GEMMs, validated numerics) + cp.async pipeline
// ---------------------------------------------------------------------------

#define Bn  4
#define Ln  2048
#define Dn  512
#define Hn  8
#define NBD (Bn * Ln * Dn)   // 4,194,304

__device__ float  g_v0[NBD];
__device__ float  g_v1[NBD];
__device__ float  g_v2[NBD];
__device__ float  g_q [NBD];
__device__ float  g_vv[NBD];
__device__ __half g_kh [NBD];   // K hi, [B][L][D]
__device__ __half g_kl [NBD];   // K lo
__device__ __half g_vth[NBD];   // V^T hi, [B*H][64][L]
__device__ __half g_vtl[NBD];   // V^T lo

// ---------------------------------------------------------------------------
__device__ __forceinline__ void split_h2(float x, float y,
                                         unsigned& hi, unsigned& lo) {
    __half hx = __float2half_rn(x);
    __half hy = __float2half_rn(y);
    __half lx = __float2half_rn(x - __half2float(hx));
    __half ly = __float2half_rn(y - __half2float(hy));
    hi = ((unsigned)__half_as_ushort(hy) << 16) | __half_as_ushort(hx);
    lo = ((unsigned)__half_as_ushort(ly) << 16) | __half_as_ushort(lx);
}

__device__ __forceinline__ void mma_f16(float* c, const unsigned* a,
                                        unsigned b0, unsigned b1) {
    asm("mma.sync.aligned.m16n8k16.row.col.f32.f16.f16.f32 "
        "{%0,%1,%2,%3}, {%4,%5,%6,%7}, {%8,%9}, {%0,%1,%2,%3};"
        : "+f"(c[0]), "+f"(c[1]), "+f"(c[2]), "+f"(c[3])
        : "r"(a[0]), "r"(a[1]), "r"(a[2]), "r"(a[3]), "r"(b0), "r"(b1));
}

__device__ __forceinline__ uint32_t s2u(const void* p) {
    uint32_t a;
    asm("{ .reg .u64 t; cvta.to.shared.u64 t, %1; cvt.u32.u64 %0, t; }"
        : "=r"(a) : "l"(p));
    return a;
}

#define CP_ASYNC16(daddr, src)                                                 \
    asm volatile("cp.async.cg.shared.global [%0], [%1], 16;"                   \
                 :: "r"(daddr), "l"(src))
#define CP_COMMIT()  asm volatile("cp.async.commit_group;" ::: "memory")
#define CP_WAIT0()   asm volatile("cp.async.wait_group 0;" ::: "memory")

// ---------------------------------------------------------------------------
// 8-tap circular dilated convs (validated rounds 1-4)
// ---------------------------------------------------------------------------
__global__ __launch_bounds__(256) void conv1_kernel(
    const float* __restrict__ in, float* __restrict__ out,
    const float* __restrict__ frow, int dil)
{
    int idx4 = blockIdx.x * 256 + threadIdx.x;
    int d4 = idx4 & 127;
    int t  = (idx4 >> 7) & (Ln - 1);
    int b  = idx4 >> 18;
    const float* inb = in + ((long)b << 20) + (d4 << 2);
    float4 acc = {0.f, 0.f, 0.f, 0.f};
#pragma unroll
    for (int k = 0; k < 8; k++) {
        float tap = __ldg(&frow[(Ln - dil * k) & (Ln - 1)]);
        int src = (t - dil * k) & (Ln - 1);
        float4 v = *(const float4*)(inb + (src << 9));
        acc.x += tap * v.x; acc.y += tap * v.y;
        acc.z += tap * v.z; acc.w += tap * v.w;
    }
    *(float4*)(out + ((long)idx4 << 2)) = acc;
}

__global__ __launch_bounds__(256) void conv2_kernel(
    const float* __restrict__ in,
    float* __restrict__ outA, const float* __restrict__ frowA, int dilA,
    float* __restrict__ outB, const float* __restrict__ frowB, int dilB)
{
    int idx4 = blockIdx.x * 256 + threadIdx.x;
    int d4 = idx4 & 127;
    int t  = (idx4 >> 7) & (Ln - 1);
    int b  = idx4 >> 18;
    const float* inb = in + ((long)b << 20) + (d4 << 2);
    float4 aA = {0.f, 0.f, 0.f, 0.f};
    float4 aB = {0.f, 0.f, 0.f, 0.f};
#pragma unroll
    for (int k = 0; k < 8; k++) {
        float tap = __ldg(&frowA[(Ln - dilA * k) & (Ln - 1)]);
        int src = (t - dilA * k) & (Ln - 1);
        float4 v = *(const float4*)(inb + (src << 9));
        aA.x += tap * v.x; aA.y += tap * v.y;
        aA.z += tap * v.z; aA.w += tap * v.w;
    }
#pragma unroll
    for (int k = 0; k < 8; k++) {
        float tap = __ldg(&frowB[(Ln - dilB * k) & (Ln - 1)]);
        int src = (t - dilB * k) & (Ln - 1);
        float4 v = *(const float4*)(inb + (src << 9));
        aB.x += tap * v.x; aB.y += tap * v.y;
        aB.z += tap * v.z; aB.w += tap * v.w;
    }
    *(float4*)(outA + ((long)idx4 << 2)) = aA;
    *(float4*)(outB + ((long)idx4 << 2)) = aB;
}

__global__ __launch_bounds__(256) void conv2s_kernel(
    const float* __restrict__ in,
    __half* __restrict__ outAh, __half* __restrict__ outAl,
    const float* __restrict__ frowA, int dilA,
    float* __restrict__ outB, const float* __restrict__ frowB, int dilB)
{
    int idx4 = blockIdx.x * 256 + threadIdx.x;
    int d4 = idx4 & 127;
    int t  = (idx4 >> 7) & (Ln - 1);
    int b  = idx4 >> 18;
    const float* inb = in + ((long)b << 20) + (d4 << 2);
    float4 aA = {0.f, 0.f, 0.f, 0.f};
    float4 aB = {0.f, 0.f, 0.f, 0.f};
#pragma unroll
    for (int k = 0; k < 8; k++) {
        float tap = __ldg(&frowA[(Ln - dilA * k) & (Ln - 1)]);
        int src = (t - dilA * k) & (Ln - 1);
        float4 v = *(const float4*)(inb + (src << 9));
        aA.x += tap * v.x; aA.y += tap * v.y;
        aA.z += tap * v.z; aA.w += tap * v.w;
    }
#pragma unroll
    for (int k = 0; k < 8; k++) {
        float tap = __ldg(&frowB[(Ln - dilB * k) & (Ln - 1)]);
        int src = (t - dilB * k) & (Ln - 1);
        float4 v = *(const float4*)(inb + (src << 9));
        aB.x += tap * v.x; aB.y += tap * v.y;
        aB.z += tap * v.z; aB.w += tap * v.w;
    }
    unsigned h01, l01, h23, l23;
    split_h2(aA.x, aA.y, h01, l01);
    split_h2(aA.z, aA.w, h23, l23);
    *(uint2*)(outAh + ((long)idx4 << 2)) = make_uint2(h01, h23);
    *(uint2*)(outAl + ((long)idx4 << 2)) = make_uint2(l01, l23);
    *(float4*)(outB + ((long)idx4 << 2)) = aB;
}

__global__ __launch_bounds__(256) void vtrans_kernel(
    const float* __restrict__ v,
    __half* __restrict__ vth, __half* __restrict__ vtl)
{
    __shared__ float tile[64][65];
    int t0 = blockIdx.x * 64;
    int bh = blockIdx.y;
    int b = bh >> 3, h = bh & 7;
    const float* src = v + ((long)b * Ln + t0) * Dn + h * 64;
#pragma unroll
    for (int it = 0; it < 16; it++) {
        int o = it * 256 + threadIdx.x;
        int r = o >> 6, c = o & 63;
        tile[r][c] = src[(long)r * Dn + c];
    }
    __syncthreads();
    __half* dh_ = vth + (long)bh * 64 * Ln + t0;
    __half* dl_ = vtl + (long)bh * 64 * Ln + t0;
#pragma unroll
    for (int it = 0; it < 16; it++) {
        int o = it * 256 + threadIdx.x;
        int key = o & 63, dh = o >> 6;
        float x = tile[key][dh];
        __half hi = __float2half_rn(x);
        __half lo = __float2half_rn(x - __half2float(hi));
        dh_[(long)dh * Ln + key] = hi;
        dl_[(long)dh * Ln + key] = lo;
    }
}

// ---------------------------------------------------------------------------
// fp16 3x-split flash attention (both GEMMs), cp.async double-buffered K/V.
// Grid (L/128, B*H), 256 threads = 8 warps; warp owns 16 q-rows; BK=64.
// smem words: 2 bufs x [Kh|Kl|Vh|Vl][64][36w] + Ph[128][36w] + Pl[128][36w]
//           = 27648 words = 110,592 B  (2 CTA/SM)
// ---------------------------------------------------------------------------
#define STRW 36                    // words per smem row (72 halfs)
#define TILEW (64 * STRW)          // 2304 words per tile
#define BUFW  (4 * TILEW)          // 9216 words per buffer
#define PHOFF (2 * BUFW)           // 18432
#define PLOFF (PHOFF + 128 * STRW) // 23040
#define ASMEM ((2 * BUFW + 2 * 128 * STRW) * 4)

__global__ __launch_bounds__(256, 2) void attn_kernel(
    const float* __restrict__ Qg,
    const __half* __restrict__ Khg, const __half* __restrict__ Klg,
    const __half* __restrict__ Vhg, const __half* __restrict__ Vlg,
    float* __restrict__ O)
{
    extern __shared__ unsigned sm_u[];
    const uint32_t sb = s2u(sm_u);

    const int tid = threadIdx.x;
    const int lane = tid & 31, warp = tid >> 5;
    const int g = lane >> 2, tg = lane & 3;
    const int bh = blockIdx.y;
    const int b = bh >> 3, h = bh & 7;
    const int q0 = blockIdx.x * 128;

    // ---- Q fragments from global (scaled, split hi/lo)
    unsigned qah[4][4], qal[4][4];
    {
        const float* Qp = Qg + ((long)b * Ln + q0 + warp * 16) * Dn + h * 64;
#pragma unroll
        for (int kt = 0; kt < 4; kt++)
#pragma unroll
            for (int part = 0; part < 4; part++) {
                int row = g + (part & 1) * 8;
                int col = kt * 16 + ((part >> 1) << 3) + 2 * tg;
                float2 x = *(const float2*)(Qp + row * Dn + col);
                split_h2(x.x * 0.125f, x.y * 0.125f, qah[kt][part], qal[kt][part]);
            }
    }

    const __half* Kb  = Khg + (long)b * Ln * Dn + h * 64;
    const __half* Klb = Klg + (long)b * Ln * Dn + h * 64;
    const __half* Vb  = Vhg + (long)bh * 64 * Ln;
    const __half* Vlb = Vlg + (long)bh * 64 * Ln;

    // per-thread cp.async slice: 8 chunks of 16B covering 4 tiles x 64 rows x 8
    auto issue_copy = [&](int tile, int bufsel) {
        const int k0 = tile * 64;
        const uint32_t bufbase = sb + (uint32_t)(bufsel * BUFW) * 4u;
#pragma unroll
        for (int j = 0; j < 8; j++) {
            int flat = j * 256 + tid;
            int arr = flat >> 9, rem = flat & 511;
            int row = rem >> 3, c = rem & 7;
            const __half* src;
            uint32_t doff;
            if (arr == 0)      { src = Kb  + (long)(k0 + row) * Dn + c * 8; doff = 0; }
            else if (arr == 1) { src = Klb + (long)(k0 + row) * Dn + c * 8; doff = TILEW; }
            else if (arr == 2) { src = Vb  + (long)row * Ln + k0 + c * 8;   doff = 2 * TILEW; }
            else               { src = Vlb + (long)row * Ln + k0 + c * 8;   doff = 3 * TILEW; }
            uint32_t daddr = bufbase + (doff + row * STRW + c * 4) * 4u;
            CP_ASYNC16(daddr, src);
        }
        CP_COMMIT();
    };

    float m_[2] = {-1e30f, -1e30f}, l_[2] = {0.f, 0.f};
    float oacc[8][4];
#pragma unroll
    for (int nt = 0; nt < 8; nt++)
#pragma unroll
        for (int j = 0; j < 4; j++) oacc[nt][j] = 0.f;

    unsigned* p0h = sm_u + PHOFF + (warp * 16 + g) * STRW;
    unsigned* p1h = p0h + 8 * STRW;
    unsigned* p0l = sm_u + PLOFF + (warp * 16 + g) * STRW;
    unsigned* p1l = p0l + 8 * STRW;

    issue_copy(0, 0);   // prologue: tile 0 -> buf 0

    for (int it = 0; it < 32; it++) {
        CP_WAIT0();          // my chunks of tile `it` have landed
        __syncthreads();     // all threads' chunks visible; prev compute done
        if (it < 31) issue_copy(it + 1, (it + 1) & 1);

        unsigned* buf = sm_u + (it & 1) * BUFW;
        unsigned* sKh = buf;
        unsigned* sKl = buf + TILEW;
        unsigned* sVh = buf + 2 * TILEW;
        unsigned* sVl = buf + 3 * TILEW;

        // ---- S = Q K^T  (fp16 3x: lo*hi + hi*lo + hi*hi)
        float sc[8][4];
#pragma unroll
        for (int nt = 0; nt < 8; nt++)
            sc[nt][0] = sc[nt][1] = sc[nt][2] = sc[nt][3] = 0.f;
#pragma unroll
        for (int kt = 0; kt < 4; kt++)
#pragma unroll
            for (int nt = 0; nt < 8; nt++) {
                const unsigned* krh = sKh + (nt * 8 + g) * STRW + kt * 8;
                const unsigned* krl = sKl + (nt * 8 + g) * STRW + kt * 8;
                unsigned b0h = krh[tg], b1h = krh[tg + 4];
                unsigned b0l = krl[tg], b1l = krl[tg + 4];
                mma_f16(sc[nt], qal[kt], b0h, b1h);
                mma_f16(sc[nt], qah[kt], b0l, b1l);
                mma_f16(sc[nt], qah[kt], b0h, b1h);
            }

        // ---- online softmax (rows g, g+8 of this warp)
        float rmax[2] = {-1e30f, -1e30f};
#pragma unroll
        for (int nt = 0; nt < 8; nt++) {
            rmax[0] = fmaxf(rmax[0], fmaxf(sc[nt][0], sc[nt][1]));
            rmax[1] = fmaxf(rmax[1], fmaxf(sc[nt][2], sc[nt][3]));
        }
#pragma unroll
        for (int o = 1; o <= 2; o <<= 1) {
            rmax[0] = fmaxf(rmax[0], __shfl_xor_sync(0xffffffffu, rmax[0], o));
            rmax[1] = fmaxf(rmax[1], __shfl_xor_sync(0xffffffffu, rmax[1], o));
        }
        float corr[2];
#pragma unroll
        for (int r = 0; r < 2; r++) {
            float mn = fmaxf(m_[r], rmax[r]);
            corr[r] = __expf(m_[r] - mn);
            m_[r] = mn;
        }
        float rsum[2] = {0.f, 0.f};
#pragma unroll
        for (int nt = 0; nt < 8; nt++) {
            float p0 = __expf(sc[nt][0] - m_[0]);
            float p1 = __expf(sc[nt][1] - m_[0]);
            float p2 = __expf(sc[nt][2] - m_[1]);
            float p3 = __expf(sc[nt][3] - m_[1]);
            rsum[0] += p0 + p1; rsum[1] += p2 + p3;
            unsigned h01, l01, h23, l23;
            split_h2(p0, p1, h01, l01);
            split_h2(p2, p3, h23, l23);
            p0h[nt * 4 + tg] = h01; p0l[nt * 4 + tg] = l01;
            p1h[nt * 4 + tg] = h23; p1l[nt * 4 + tg] = l23;
        }
#pragma unroll
        for (int o = 1; o <= 2; o <<= 1) {
            rsum[0] += __shfl_xor_sync(0xffffffffu, rsum[0], o);
            rsum[1] += __shfl_xor_sync(0xffffffffu, rsum[1], o);
        }
        l_[0] = l_[0] * corr[0] + rsum[0];
        l_[1] = l_[1] * corr[1] + rsum[1];
#pragma unroll
        for (int nt = 0; nt < 8; nt++) {
            oacc[nt][0] *= corr[0]; oacc[nt][1] *= corr[0];
            oacc[nt][2] *= corr[1]; oacc[nt][3] *= corr[1];
        }
        __syncwarp();   // P rows are per-warp

        // ---- O += P V  (fp16 3x: Pl*Vh + Ph*Vl + Ph*Vh)
#pragma unroll
        for (int kt = 0; kt < 4; kt++) {
            unsigned pah[4], pal[4];
            pah[0] = p0h[kt * 8 + tg];     pal[0] = p0l[kt * 8 + tg];
            pah[1] = p1h[kt * 8 + tg];     pal[1] = p1l[kt * 8 + tg];
            pah[2] = p0h[kt * 8 + tg + 4]; pal[2] = p0l[kt * 8 + tg + 4];
            pah[3] = p1h[kt * 8 + tg + 4]; pal[3] = p1l[kt * 8 + tg + 4];
#pragma unroll
            for (int nt = 0; nt < 8; nt++) {
                const unsigned* vrh = sVh + (nt * 8 + g) * STRW + kt * 8;
                const unsigned* vrl = sVl + (nt * 8 + g) * STRW + kt * 8;
                unsigned b0h = vrh[tg], b1h = vrh[tg + 4];
                unsigned b0l = vrl[tg], b1l = vrl[tg + 4];
                mma_f16(oacc[nt], pal, b0h, b1h);
                mma_f16(oacc[nt], pah, b0l, b1l);
                mma_f16(oacc[nt], pah, b0h, b1h);
            }
        }
    }

    // ---- epilogue
    float inv0 = 1.f / l_[0], inv1 = 1.f / l_[1];
    long row0 = (long)b * Ln + q0 + warp * 16 + g;
    long row1 = row0 + 8;
#pragma unroll
    for (int nt = 0; nt < 8; nt++) {
        int col = h * 64 + nt * 8 + 2 * tg;
        float2 v0 = {oacc[nt][0] * inv0, oacc[nt][1] * inv0};
        float2 v1 = {oacc[nt][2] * inv1, oacc[nt][3] * inv1};
        *(float2*)(O + row0 * Dn + col) = v0;
        *(float2*)(O + row1 * Dn + col) = v1;
    }
}

// ---------------------------------------------------------------------------
extern "C" void kernel_launch(void* const* d_in, const int* in_sizes, int n_in,
                              void* d_out, int out_size)
{
    const float* x  = (const float*)d_in[0];
    const float* vf = (const float*)d_in[1];
    const float* wf = (const float*)d_in[2];
    float* out = (float*)d_out;

    float *v0, *v1, *v2, *q, *vv;
    __half *kh, *kl, *vth, *vtl;
    cudaGetSymbolAddress((void**)&v0,  g_v0);
    cudaGetSymbolAddress((void**)&v1,  g_v1);
    cudaGetSymbolAddress((void**)&v2,  g_v2);
    cudaGetSymbolAddress((void**)&q,   g_q);
    cudaGetSymbolAddress((void**)&vv,  g_vv);
    cudaGetSymbolAddress((void**)&kh,  g_kh);
    cudaGetSymbolAddress((void**)&kl,  g_kl);
    cudaGetSymbolAddress((void**)&vth, g_vth);
    cudaGetSymbolAddress((void**)&vtl, g_vtl);

    const size_t LL = (size_t)Ln * Ln;
    const int cblocks = (NBD / 4) / 256;

    // v0 = L0(x); {q = H0(v0), v1 = L1(v0)}; {k = H1(v1), v2 = L2(v1)}; vv = H2(v2)
    conv1_kernel<<<cblocks, 256>>>(x, v0, vf, 1);
    conv2_kernel<<<cblocks, 256>>>(v0, q, wf, 1, v1, vf + LL, 2);
    conv2s_kernel<<<cblocks, 256>>>(v1, kh, kl, wf + LL, 2, v2, vf + 2 * LL, 4);
    conv1_kernel<<<cblocks, 256>>>(v2, vv, wf + 2 * LL, 4);
    vtrans_kernel<<<dim3(Ln / 64, Bn * Hn), 256>>>(vv, vth, vtl);

    cudaFuncSetAttribute(attn_kernel,
                         cudaFuncAttributeMaxDynamicSharedMemorySize, ASMEM);
    dim3 grid(Ln / 128, Bn * Hn);   // (16, 32)
    attn_kernel<<<grid, 256, ASMEM>>>(q, kh, kl, vth, vtl, out);
}